// round 16
// baseline (speedup 1.0000x reference)
#include <cuda_runtime.h>
#include <cstdint>

#define VOCAB 67
#define EMB 50
#define NLAYERS 8
#define ROWF 80               // floats per padded row (32B-aligned stride)
#define REP8 (VOCAB*ROWF)     // 5360 floats per replica
#define TAB8_FLOATS (8*REP8)  // 8 shifted replicas, 171.5 KB

// 8 shifted replicas: replica p stores row element e at padded slot e+p.
__device__ __align__(32) float g_tab8[TAB8_FLOATS];

// ---------------------------------------------------------------------------
// cp.async helpers
// ---------------------------------------------------------------------------
__device__ __forceinline__ void cp16(uint32_t s, const void* g) {
    asm volatile("cp.async.cg.shared.global [%0], [%1], 16;" :: "r"(s), "l"(g));
}
__device__ __forceinline__ void cp_commit() { asm volatile("cp.async.commit_group;"); }
template<int N> __device__ __forceinline__ void cp_wait() {
    asm volatile("cp.async.wait_group %0;" :: "n"(N));
}

// ---------------------------------------------------------------------------
// Kernel 1: per-token logits table — verified R7 compute; only the final
// writes change (8 shifted replicas instead of 4).
// ---------------------------------------------------------------------------
__global__ void __launch_bounds__(128) table_kernel(
    const float* __restrict__ emb,   // [67,50]
    const float* __restrict__ kappa, // [8,50,50]
    const float* __restrict__ phi,   // [8,50,50]
    const float* __restrict__ W_out, // [50,67]
    const float* __restrict__ b_out) // [67]
{
    const int t   = blockIdx.x;
    const int tid = threadIdx.x;

    __shared__ __align__(16) float wK[2][EMB*EMB], wP[2][EMB*EMB];  // 40 KB
    __shared__ float sar[2][EMB], sai[2][EMB], sint[EMB];

    const uint32_t sK0 = (uint32_t)__cvta_generic_to_shared(&wK[0][0]);
    const uint32_t sK1 = (uint32_t)__cvta_generic_to_shared(&wK[1][0]);
    const uint32_t sP0 = (uint32_t)__cvta_generic_to_shared(&wP[0][0]);
    const uint32_t sP1 = (uint32_t)__cvta_generic_to_shared(&wP[1][0]);

    if (tid < EMB) { sar[0][tid] = emb[t*EMB + tid]; sai[0][tid] = 0.f; }

    #pragma unroll
    for (int i = 0; i < 5; ++i) {
        int j = tid + i*128;
        if (j < 625) {
            cp16(sK0 + j*16, kappa + j*4);
            cp16(sP0 + j*16, phi   + j*4);
        }
    }
    cp_commit();

    for (int l = 0; l < NLAYERS; ++l) {
        const int buf = l & 1;
        if (l + 1 < NLAYERS) {
            const uint32_t dK = (buf ? sK0 : sK1), dP = (buf ? sP0 : sP1);
            const float* gK = kappa + (l+1)*EMB*EMB;
            const float* gP = phi   + (l+1)*EMB*EMB;
            #pragma unroll
            for (int i = 0; i < 5; ++i) {
                int j = tid + i*128;
                if (j < 625) {
                    cp16(dK + j*16, gK + j*4);
                    cp16(dP + j*16, gP + j*4);
                }
            }
            cp_commit();
            cp_wait<1>();
        } else {
            cp_wait<0>();
        }
        __syncthreads();

        const int cur = l & 1, nxt = cur ^ 1;
        const float* K = wK[buf];
        const float* P = wP[buf];
        if (tid < EMB) {                       // real, f = tid
            float a0=0.f,a1=0.f,a2=0.f,a3=0.f;
            #pragma unroll
            for (int e = 0; e < 48; e += 4) {
                a0 += sar[cur][e+0]*K[(e+0)*EMB+tid] - sai[cur][e+0]*P[(e+0)*EMB+tid];
                a1 += sar[cur][e+1]*K[(e+1)*EMB+tid] - sai[cur][e+1]*P[(e+1)*EMB+tid];
                a2 += sar[cur][e+2]*K[(e+2)*EMB+tid] - sai[cur][e+2]*P[(e+2)*EMB+tid];
                a3 += sar[cur][e+3]*K[(e+3)*EMB+tid] - sai[cur][e+3]*P[(e+3)*EMB+tid];
            }
            a0 += sar[cur][48]*K[48*EMB+tid] - sai[cur][48]*P[48*EMB+tid];
            a1 += sar[cur][49]*K[49*EMB+tid] - sai[cur][49]*P[49*EMB+tid];
            sar[nxt][tid] = (a0+a1) + (a2+a3);
        } else if (tid >= 64 && tid < 64 + EMB) {  // imag, f = tid-64
            const int f = tid - 64;
            float a0=0.f,a1=0.f,a2=0.f,a3=0.f;
            #pragma unroll
            for (int e = 0; e < 48; e += 4) {
                a0 += sar[cur][e+0]*P[(e+0)*EMB+f] + sai[cur][e+0]*K[(e+0)*EMB+f];
                a1 += sar[cur][e+1]*P[(e+1)*EMB+f] + sai[cur][e+1]*K[(e+1)*EMB+f];
                a2 += sar[cur][e+2]*P[(e+2)*EMB+f] + sai[cur][e+2]*K[(e+2)*EMB+f];
                a3 += sar[cur][e+3]*P[(e+3)*EMB+f] + sai[cur][e+3]*K[(e+3)*EMB+f];
            }
            a0 += sar[cur][48]*P[48*EMB+f] + sai[cur][48]*K[48*EMB+f];
            a1 += sar[cur][49]*P[49*EMB+f] + sai[cur][49]*K[49*EMB+f];
            sai[nxt][f] = (a0+a1) + (a2+a3);
        }
        __syncthreads();
    }

    if (tid < EMB) {
        float a = sar[0][tid], b = sai[0][tid];
        sint[tid] = a*a + b*b;
    }
    __syncthreads();
    if (tid < VOCAB) {
        float acc = __ldg(b_out + tid);
        #pragma unroll
        for (int e = 0; e < EMB; ++e)
            acc += sint[e] * __ldg(W_out + e*VOCAB + tid);
        #pragma unroll
        for (int p = 0; p < 8; ++p)
            g_tab8[p*REP8 + t*ROWF + tid + p] = acc;
    }
}

// ---------------------------------------------------------------------------
// Kernel 2: gather with 256-bit memory ops (sm_100+). One warp = 32 tokens
// = 268 float8 chunks. Lane owns chunk p8 = lane + 32*i (9 iters, last
// partial). Main read: ONE aligned ld.global.v8 from replica j=(3*tk)&7
// (slot r+j is 8-aligned). Straddle (r>=60): one aligned v8 from replica
// s=67-r of next token's row start -> w[m] holds element m-s, merge is 7
// predicated selects. Stores: st.global.cs.v8 (evict-first, verified).
// idx loads use .cs so the 2MB index stream doesn't evict the table from L1.
// ---------------------------------------------------------------------------
__device__ __forceinline__ void ldg256(const float* p, float* v) {
    asm("ld.global.v8.f32 {%0,%1,%2,%3,%4,%5,%6,%7}, [%8];"
        : "=f"(v[0]), "=f"(v[1]), "=f"(v[2]), "=f"(v[3]),
          "=f"(v[4]), "=f"(v[5]), "=f"(v[6]), "=f"(v[7]) : "l"(p));
}
__device__ __forceinline__ void stcs256(float* p, const float* v) {
    asm volatile("st.global.cs.v8.f32 [%0], {%1,%2,%3,%4,%5,%6,%7,%8};"
                 :: "l"(p), "f"(v[0]), "f"(v[1]), "f"(v[2]), "f"(v[3]),
                    "f"(v[4]), "f"(v[5]), "f"(v[6]), "f"(v[7]) : "memory");
}
__device__ __forceinline__ int ldcs_i32(const int* p) {
    int v;
    asm("ld.global.cs.b32 %0, [%1];" : "=r"(v) : "l"(p));
    return v;
}

__global__ void __launch_bounds__(256) gather_kernel(
    const int* __restrict__ idx, float* __restrict__ out)
{
    const int lane = threadIdx.x & 31;
    const int warp = (blockIdx.x * 256 + (int)threadIdx.x) >> 5;   // 0..16383

    const int mytok = ldcs_i32(idx + warp*32 + lane);    // token ids < 67
    const int nxt   = __shfl_down_sync(0xffffffffu, mytok, 1);
    const int pair  = mytok | (nxt << 8);                // {tok[lane], tok[lane+1]}
    float* O = out + (uint32_t)warp * 2144;

    #pragma unroll
    for (int i = 0; i < 9; ++i) {
        const int p8 = lane + 32*i;          // output float8 index
        const int e0 = 8*p8;
        const int tk = (int)((unsigned)e0 / 67u);  // owning token slot
        const int r  = e0 - 67*tk;           // element offset within token row

        const int pp     = __shfl_sync(0xffffffffu, pair, tk & 31);
        const int token  = pp & 0xff;
        const int token2 = (pp >> 8) & 0xff;

        const int j   = (3*tk) & 7;          // replica: (r+j) % 8 == 0
        const int pos = r + j;               // 32B-aligned slot
        float v[8];
        ldg256(g_tab8 + j*REP8 + token*ROWF + pos, v);

        if (r >= 60) {                       // straddle: elements r..66 | 0..r-60
            const int s = 67 - r;            // 1..7
            float w[8];
            ldg256(g_tab8 + s*REP8 + token2*ROWF, w);   // w[m] = token2 elem m-s
            if (r == 66) v[1] = w[1];
            if (r >= 65) v[2] = w[2];
            if (r >= 64) v[3] = w[3];
            if (r >= 63) v[4] = w[4];
            if (r >= 62) v[5] = w[5];
            if (r >= 61) v[6] = w[6];
            v[7] = w[7];                     // m=7 always crosses when r>=60
        }
        if (i < 8 || lane < 12)              // chunks >=268 don't exist
            stcs256(O + 8*p8, v);
    }
}

// ---------------------------------------------------------------------------
// Launch: plain back-to-back launches (PDL verified harmful in R6 and R15).
// ---------------------------------------------------------------------------
extern "C" void kernel_launch(void* const* d_in, const int* in_sizes, int n_in,
                              void* d_out, int out_size) {
    const int*   idx = (const int*)d_in[0];   // input_seq [64,8192] int32
    const float* emb = (const float*)d_in[1]; // embedding_table [67,50]
    const float* kap = (const float*)d_in[2]; // kappa [8,50,50]
    const float* ph  = (const float*)d_in[3]; // phi   [8,50,50]
    const float* Wo  = (const float*)d_in[4]; // W_out [50,67]
    const float* bo  = (const float*)d_in[5]; // b_out [67]
    float* out = (float*)d_out;

    table_kernel<<<VOCAB, 128>>>(emb, kap, ph, Wo, bo);
    gather_kernel<<<2048, 256>>>(idx, out);   // 16384 warps, one 32-token tile each
}